// round 16
// baseline (speedup 1.0000x reference)
#include <cuda_runtime.h>
#include <cstdint>

#define Nn     8192
#define IND    128
#define HID    32
#define BM     128
#define KSPLIT 16
#define KCHUNK (Nn / KSPLIT)      // 512
#define NTILE  (KCHUNK / 64)      // 8 tiles of k=64

// Scratch (static device arrays only; no allocations)
// g_adjq is stored PERMUTED: within each 32-byte k-group G, word order is
// [k0-3][k16-19][k4-7][k20-23][k8-11][k24-27][k12-15][k28-31], so an MMA
// A-fragment (a0,a2) pair for thread c is 8 contiguous bytes at 32G+8c.
__device__ unsigned char g_adjq[(size_t)Nn * Nn];     // u8 adj, permuted (64 MB)
__device__ float         g_dinv[Nn];
__device__ float         g_zs[Nn * HID];              // fp32 zs (exact self-loop)
__device__ signed char   g_zqT[(size_t)HID * Nn];     // s8 zs transposed [c][j]
__device__ int           g_acc[2][Nn * HID];          // s32 accumulators (2x1MB)
__device__ unsigned      g_cmbits[2][HID];            // per-col absmax (uint bits)
// g_cmbits: zero at module load, atomicMax'ed with per-call-identical values ->
// steady state == first-call result: deterministic across graph replays.
// g_acc: re-zeroed inside degree_convert_kernel (blocks 0..511) every call;
// accumulated with s32 atomicAdd (exact, order-independent) -> deterministic.

// ---------------------------------------------------------------------------
__device__ __forceinline__ uint32_t smem_u32(const void* p) {
    uint32_t a;
    asm("{ .reg .u64 t; cvta.to.shared.u64 t, %1; cvt.u32.u64 %0, t; }" : "=r"(a) : "l"(p));
    return a;
}
__device__ __forceinline__ void cp16(uint32_t dst, const void* src) {
    asm volatile("cp.async.cg.shared.global [%0], [%1], 16;" :: "r"(dst), "l"(src));
}

// ---------------------------------------------------------------------------
// 1) degree + u8 convert (one row per block): dinv=rsqrt(max(1,1+rowsum)),
//    adjq = round(adj*255) stored with the fragment permutation.
//    Blocks 0..511 also zero the 2MB of s32 accumulators (consumed later).
// ---------------------------------------------------------------------------
__global__ __launch_bounds__(256) void degree_convert_kernel(const float* __restrict__ adj) {
    if (blockIdx.x < 512) {
        int i = blockIdx.x * 256 + threadIdx.x;      // 131072 int4 = 2 MB
        reinterpret_cast<int4*>(g_acc)[i] = make_int4(0, 0, 0, 0);
    }
    int row = blockIdx.x;
    const float4* rp = reinterpret_cast<const float4*>(adj + (size_t)row * Nn);
    uchar4* qp = reinterpret_cast<uchar4*>(g_adjq + (size_t)row * Nn);
    float s = 0.f;
    for (int i = threadIdx.x; i < Nn / 4; i += 256) {
        float4 v = rp[i];
        s += (v.x + v.y) + (v.z + v.w);
        uchar4 q;
        q.x = (unsigned char)__float2int_rn(v.x * 255.f);
        q.y = (unsigned char)__float2int_rn(v.y * 255.f);
        q.z = (unsigned char)__float2int_rn(v.z * 255.f);
        q.w = (unsigned char)__float2int_rn(v.w * 255.f);
        int G = i >> 3, cc = i & 7;
        int w = (cc < 4) ? (8 * G + 2 * cc) : (8 * G + 2 * (cc - 4) + 1);
        qp[w] = q;
    }
#pragma unroll
    for (int o = 16; o; o >>= 1) s += __shfl_down_sync(0xffffffffu, s, o);
    __shared__ float ws[8];
    int lane = threadIdx.x & 31, w = threadIdx.x >> 5;
    if (lane == 0) ws[w] = s;
    __syncthreads();
    if (threadIdx.x == 0) {
        float d = 1.0f;  // self loop
#pragma unroll
        for (int i = 0; i < 8; i++) d += ws[i];
        d = fmaxf(d, 1.0f);
        g_dinv[row] = rsqrtf(d);
    }
}

// ---------------------------------------------------------------------------
// 2) zs = dinv ⊙ (x @ W1 + b1)   ; fp32 g_zs + colmax[0]
// ---------------------------------------------------------------------------
__global__ __launch_bounds__(256) void z1_kernel(const float* __restrict__ x,
                                                 const float* __restrict__ W1,
                                                 const float* __restrict__ b1) {
    __shared__ float Ws[IND * HID];
    __shared__ float xs[8][IND];
    __shared__ float red[256];
    int tid = threadIdx.x;
    int row0 = blockIdx.x * 8;
    for (int i = tid; i < IND * HID; i += 256) Ws[i] = W1[i];
    for (int i = tid; i < 8 * IND; i += 256)
        xs[i >> 7][i & 127] = x[(size_t)(row0 + (i >> 7)) * IND + (i & 127)];
    __syncthreads();
    int r = tid >> 5, c = tid & 31;
    float acc = b1[c];
#pragma unroll 8
    for (int k = 0; k < IND; k++) acc += xs[r][k] * Ws[k * HID + c];
    int row = row0 + r;
    float v = g_dinv[row] * acc;
    g_zs[row * HID + c] = v;
    red[tid] = fabsf(v);
    __syncthreads();
    if (tid < 128) red[tid] = fmaxf(red[tid], red[tid + 128]);
    __syncthreads();
    if (tid < 64) red[tid] = fmaxf(red[tid], red[tid + 64]);
    __syncthreads();
    if (tid < 32) atomicMax(&g_cmbits[0][tid], __float_as_uint(fmaxf(red[tid], red[tid + 32])));
}

// ---------------------------------------------------------------------------
// Quantize+transpose: g_zqT[c][j] = round(zs[j][c] * 127/cmax_c)
//   32 rows per block, 128 threads, 256 blocks (latency fix: 2x parallelism)
// ---------------------------------------------------------------------------
__global__ __launch_bounds__(128) void quantT_kernel(int layer) {
    __shared__ float tile[32][HID + 1];
    __shared__ float rcp_s[HID];
    int tid = threadIdx.x;
    int row0 = blockIdx.x * 32;
    if (tid < HID)
        rcp_s[tid] = 127.f / fmaxf(__uint_as_float(g_cmbits[layer][tid]), 1e-20f);
    for (int i = tid; i < 32 * 8; i += 128) {
        int r = i >> 3, c4 = (i & 7) << 2;
        float4 v = *reinterpret_cast<const float4*>(&g_zs[(size_t)(row0 + r) * HID + c4]);
        tile[r][c4 + 0] = v.x; tile[r][c4 + 1] = v.y;
        tile[r][c4 + 2] = v.z; tile[r][c4 + 3] = v.w;
    }
    __syncthreads();
    int col = tid >> 2, jb = (tid & 3) * 8;
    float rcp = rcp_s[col];
    signed char q[8];
#pragma unroll
    for (int j = 0; j < 8; j++)
        q[j] = (signed char)__float2int_rn(tile[jb + j][col] * rcp);
    *reinterpret_cast<int2*>(&g_zqT[(size_t)col * Nn + row0 + jb]) =
        *reinterpret_cast<int2*>(q);
}

// ---------------------------------------------------------------------------
// 3+5) adjq @ zqT^T via mma m16n8k32 u8.s8, accumulated with RED.s32 into
//      g_acc[layer]. Proven config (grid 1024, 16KB B smem, one barrier,
//      depth-1 A ping-pong, permuted LDG.64 A fragments).
// ---------------------------------------------------------------------------
__global__ void __launch_bounds__(256) spmm_mma_kernel(int layer) {
    __shared__ __align__(16) unsigned char sB[HID * KCHUNK];  // 16 KB

    const int tid  = threadIdx.x;
    const int wid  = tid >> 5;
    const int lane = tid & 31;
    const int mb   = blockIdx.x >> 4;
    const int ks   = blockIdx.x & (KSPLIT - 1);
    const int row0 = mb * BM;
    const int k0   = ks * KCHUNK;
    const uint32_t sbase = smem_u32(sB);
    const int m0 = wid * 16;

    // ---- load full B chunk: 32 rows x 32 chunks of 16B, swizzle chunk^row ----
#pragma unroll
    for (int i = 0; i < 4; i++) {
        const int idx = tid + i * 256;
        const int n = idx >> 5, ch = idx & 31;
        cp16(sbase + (uint32_t)(n * KCHUNK + ((ch ^ n) << 4)),
             g_zqT + (size_t)n * Nn + k0 + ch * 16);
    }
    asm volatile("cp.async.commit_group;" ::: "memory");

    // permuted A: (a0,a2) for group G at byte 32G + 8*(lane&3)
    const unsigned char* aP =
        g_adjq + (size_t)(row0 + m0 + (lane >> 2)) * Nn + k0 + 8 * (lane & 3);
    const int nA = ((lane >> 4) << 3) + (lane & 7);
    const int cb = (lane >> 3) & 1;

    asm volatile("cp.async.wait_group 0;" ::: "memory");
    __syncthreads();   // the ONLY barrier

    int c[4][4];
#pragma unroll
    for (int nt = 0; nt < 4; nt++)
#pragma unroll
        for (int j = 0; j < 4; j++) c[nt][j] = 0;

    uint2 A0[4], A1[4];
#define LDA(dst, T)                                                              \
    {                                                                            \
        const unsigned char* p = aP + (T) * 64;                                  \
        dst[0] = __ldg(reinterpret_cast<const uint2*>(p));                       \
        dst[1] = __ldg(reinterpret_cast<const uint2*>(p + (size_t)8 * Nn));      \
        dst[2] = __ldg(reinterpret_cast<const uint2*>(p + 32));                  \
        dst[3] = __ldg(reinterpret_cast<const uint2*>(p + 32 + (size_t)8 * Nn)); \
    }

    LDA(A0, 0)

#pragma unroll
    for (int t = 0; t < NTILE; t++) {
        uint2* Ac = (t & 1) ? A1 : A0;
        uint2* An = (t & 1) ? A0 : A1;
        if (t + 1 < NTILE) LDA(An, t + 1)

#pragma unroll
        for (int kk = 0; kk < 2; kk++) {
            const int cL = t * 4 + kk * 2 + cb;
            uint32_t b[4][2];
#pragma unroll
            for (int half = 0; half < 2; half++) {
                const int n = half * 16 + nA;
                const uint32_t addr = sbase + (uint32_t)(n * KCHUNK + ((cL ^ n) << 4));
                asm volatile(
                    "ldmatrix.sync.aligned.m8n8.x4.shared.b16 {%0,%1,%2,%3}, [%4];"
                    : "=r"(b[half * 2][0]), "=r"(b[half * 2][1]),
                      "=r"(b[half * 2 + 1][0]), "=r"(b[half * 2 + 1][1])
                    : "r"(addr));
            }
            const uint32_t a0 = Ac[2 * kk].x, a1 = Ac[2 * kk + 1].x;
            const uint32_t a2 = Ac[2 * kk].y, a3 = Ac[2 * kk + 1].y;
#pragma unroll
            for (int nt = 0; nt < 4; nt++) {
                asm volatile(
                    "mma.sync.aligned.m16n8k32.row.col.s32.u8.s8.s32 "
                    "{%0,%1,%2,%3}, {%4,%5,%6,%7}, {%8,%9}, {%0,%1,%2,%3};"
                    : "+r"(c[nt][0]), "+r"(c[nt][1]), "+r"(c[nt][2]), "+r"(c[nt][3])
                    : "r"(a0), "r"(a1), "r"(a2), "r"(a3),
                      "r"(b[nt][0]), "r"(b[nt][1]));
            }
        }
    }
#undef LDA

    // accumulate s32 results (m16n8 C lane layout) via RED.s32 — exact & assoc.
    int* pp = g_acc[layer];
    const int g  = lane >> 2;
    const int tg = lane & 3;
    const int rbase = row0 + m0;
#pragma unroll
    for (int nt = 0; nt < 4; nt++) {
        const int col = nt * 8 + tg * 2;
        atomicAdd(&pp[(size_t)(rbase + g) * HID + col],     c[nt][0]);
        atomicAdd(&pp[(size_t)(rbase + g) * HID + col + 1], c[nt][1]);
        atomicAdd(&pp[(size_t)(rbase + g + 8) * HID + col],     c[nt][2]);
        atomicAdd(&pp[(size_t)(rbase + g + 8) * HID + col + 1], c[nt][3]);
    }
}

// ---------------------------------------------------------------------------
// Fused: h = relu(dinv⊙(dequant(acc0)+zs));  zs' = dinv⊙(h@W2+b2); colmax[1]
//        16 rows per block, 128 threads, grid 512.
// ---------------------------------------------------------------------------
__global__ __launch_bounds__(128) void epi1_z2_kernel(const float* __restrict__ W2,
                                                      const float* __restrict__ b2) {
    __shared__ float hs[16][HID + 1];
    __shared__ float W2s[HID * HID];
    __shared__ unsigned cm[HID];
    int tid = threadIdx.x;
    int r = tid >> 3;             // 0..15
    int c0 = (tid & 7) << 2;
    int row = blockIdx.x * 16 + r;
    int idx4 = (row * HID + c0) >> 2;

    for (int i = tid; i < HID * HID; i += 128) W2s[i] = W2[i];
    if (tid < HID) cm[tid] = 0u;

    int4 S = reinterpret_cast<const int4*>(g_acc[0])[idx4];
    float4 zs = reinterpret_cast<const float4*>(g_zs)[idx4];
    float di = g_dinv[row];
    const float inv = 1.0f / 32385.0f;  // 1/(127*255)
    float f0 = __uint_as_float(g_cmbits[0][c0 + 0]) * inv;
    float f1 = __uint_as_float(g_cmbits[0][c0 + 1]) * inv;
    float f2 = __uint_as_float(g_cmbits[0][c0 + 2]) * inv;
    float f3 = __uint_as_float(g_cmbits[0][c0 + 3]) * inv;
    hs[r][c0 + 0] = fmaxf(di * (S.x * f0 + zs.x), 0.f);
    hs[r][c0 + 1] = fmaxf(di * (S.y * f1 + zs.y), 0.f);
    hs[r][c0 + 2] = fmaxf(di * (S.z * f2 + zs.z), 0.f);
    hs[r][c0 + 3] = fmaxf(di * (S.w * f3 + zs.w), 0.f);
    __syncthreads();

    float acc[4] = { b2[c0], b2[c0 + 1], b2[c0 + 2], b2[c0 + 3] };
#pragma unroll
    for (int k = 0; k < HID; k++) {
        float hv = hs[r][k];
        acc[0] += hv * W2s[k * HID + c0 + 0];
        acc[1] += hv * W2s[k * HID + c0 + 1];
        acc[2] += hv * W2s[k * HID + c0 + 2];
        acc[3] += hv * W2s[k * HID + c0 + 3];
    }
    float4 o;
    o.x = di * acc[0]; o.y = di * acc[1]; o.z = di * acc[2]; o.w = di * acc[3];
    reinterpret_cast<float4*>(g_zs)[idx4] = o;
    atomicMax(&cm[c0 + 0], __float_as_uint(fabsf(o.x)));
    atomicMax(&cm[c0 + 1], __float_as_uint(fabsf(o.y)));
    atomicMax(&cm[c0 + 2], __float_as_uint(fabsf(o.z)));
    atomicMax(&cm[c0 + 3], __float_as_uint(fabsf(o.w)));
    __syncthreads();
    if (tid < HID) atomicMax(&g_cmbits[1][tid], cm[tid]);
}

// ---------------------------------------------------------------------------
// Epilogue L2 + final: logits = relu(dinv⊙(dequant(acc1)+zs)) @ W3 + b3
// ---------------------------------------------------------------------------
__global__ __launch_bounds__(128) void epilogue_final_kernel(const float* __restrict__ W3,
                                                             const float* __restrict__ b3,
                                                             float* __restrict__ out) {
    int tid = threadIdx.x;
    int idx4 = blockIdx.x * 128 + tid;
    int row = idx4 >> 3;
    int c0 = (idx4 & 7) << 2;
    int4 S = reinterpret_cast<const int4*>(g_acc[1])[idx4];
    float4 zs = reinterpret_cast<const float4*>(g_zs)[idx4];
    float di = g_dinv[row];
    const float inv = 1.0f / 32385.0f;
    float f0 = __uint_as_float(g_cmbits[1][c0 + 0]) * inv;
    float f1 = __uint_as_float(g_cmbits[1][c0 + 1]) * inv;
    float f2 = __uint_as_float(g_cmbits[1][c0 + 2]) * inv;
    float f3 = __uint_as_float(g_cmbits[1][c0 + 3]) * inv;
    float h0 = fmaxf(di * (S.x * f0 + zs.x), 0.f);
    float h1 = fmaxf(di * (S.y * f1 + zs.y), 0.f);
    float h2 = fmaxf(di * (S.z * f2 + zs.z), 0.f);
    float h3 = fmaxf(di * (S.w * f3 + zs.w), 0.f);
    float v = h0 * W3[c0] + h1 * W3[c0 + 1] + h2 * W3[c0 + 2] + h3 * W3[c0 + 3];
#pragma unroll
    for (int o = 4; o; o >>= 1) v += __shfl_xor_sync(0xffffffffu, v, o);
    if ((tid & 7) == 0) out[row] = v + b3[0];
}

// ---------------------------------------------------------------------------
extern "C" void kernel_launch(void* const* d_in, const int* in_sizes, int n_in,
                              void* d_out, int out_size) {
    const float* x   = (const float*)d_in[0];
    const float* adj = (const float*)d_in[1];
    const float* W1  = (const float*)d_in[2];
    const float* b1  = (const float*)d_in[3];
    const float* W2  = (const float*)d_in[4];
    const float* b2  = (const float*)d_in[5];
    const float* W3  = (const float*)d_in[6];
    const float* b3  = (const float*)d_in[7];
    float* out = (float*)d_out;

    degree_convert_kernel<<<Nn, 256>>>(adj);          // also zeroes g_acc
    z1_kernel<<<Nn / 8, 256>>>(x, W1, b1);
    quantT_kernel<<<Nn / 32, 128>>>(0);
    spmm_mma_kernel<<<64 * KSPLIT, 256>>>(0);         // layer 1 -> g_acc[0]
    epi1_z2_kernel<<<Nn / 16, 128>>>(W2, b2);         // h + z2 fused -> g_zs
    quantT_kernel<<<Nn / 32, 128>>>(1);
    spmm_mma_kernel<<<64 * KSPLIT, 256>>>(1);         // layer 2 -> g_acc[1]
    epilogue_final_kernel<<<Nn * HID / 4 / 128, 128>>>(W3, b3, out);
}

// round 17
// speedup vs baseline: 1.0328x; 1.0328x over previous
#include <cuda_runtime.h>
#include <cstdint>

#define Nn     8192
#define IND    128
#define HID    32
#define BM     128
#define KSPLIT 16
#define KCHUNK (Nn / KSPLIT)      // 512
#define NTILE  (KCHUNK / 64)      // 8 tiles of k=64

// Scratch (static device arrays only; no allocations)
// g_adjq is stored PERMUTED: within each 32-byte k-group G, word order is
// [k0-3][k16-19][k4-7][k20-23][k8-11][k24-27][k12-15][k28-31], so an MMA
// A-fragment (a0,a2) pair for thread c is 8 contiguous bytes at 32G+8c.
__device__ unsigned char g_adjq[(size_t)Nn * Nn];     // u8 adj, permuted (64 MB)
__device__ float         g_dinv[Nn];
__device__ float         g_zs[Nn * HID];              // fp32 zs (exact self-loop)
__device__ signed char   g_zqT[(size_t)HID * Nn];     // s8 zs transposed [c][j]
__device__ int           g_acc[2][Nn * HID];          // s32 accumulators (2x1MB)
__device__ unsigned      g_cmbits[2][HID];            // per-col absmax (uint bits)
// g_cmbits: zero at module load, atomicMax'ed with per-call-identical values ->
// steady state == first-call result: deterministic across graph replays.
// g_acc: re-zeroed inside degree_convert_kernel (blocks 0..511) every call;
// accumulated with s32 atomicAdd (exact, order-independent) -> deterministic.

// ---------------------------------------------------------------------------
__device__ __forceinline__ uint32_t smem_u32(const void* p) {
    uint32_t a;
    asm("{ .reg .u64 t; cvta.to.shared.u64 t, %1; cvt.u32.u64 %0, t; }" : "=r"(a) : "l"(p));
    return a;
}
__device__ __forceinline__ void cp16(uint32_t dst, const void* src) {
    asm volatile("cp.async.cg.shared.global [%0], [%1], 16;" :: "r"(dst), "l"(src));
}

// ---------------------------------------------------------------------------
// 1) degree + u8 convert (one row per block): dinv=rsqrt(max(1,1+rowsum)),
//    adjq = round(adj*255) stored with the fragment permutation.
//    Blocks 0..511 also zero the 2MB of s32 accumulators (consumed later).
// ---------------------------------------------------------------------------
__global__ __launch_bounds__(256) void degree_convert_kernel(const float* __restrict__ adj) {
    if (blockIdx.x < 512) {
        int i = blockIdx.x * 256 + threadIdx.x;      // 131072 int4 = 2 MB
        reinterpret_cast<int4*>(g_acc)[i] = make_int4(0, 0, 0, 0);
    }
    int row = blockIdx.x;
    const float4* rp = reinterpret_cast<const float4*>(adj + (size_t)row * Nn);
    uchar4* qp = reinterpret_cast<uchar4*>(g_adjq + (size_t)row * Nn);
    float s = 0.f;
    for (int i = threadIdx.x; i < Nn / 4; i += 256) {
        float4 v = rp[i];
        s += (v.x + v.y) + (v.z + v.w);
        uchar4 q;
        q.x = (unsigned char)__float2int_rn(v.x * 255.f);
        q.y = (unsigned char)__float2int_rn(v.y * 255.f);
        q.z = (unsigned char)__float2int_rn(v.z * 255.f);
        q.w = (unsigned char)__float2int_rn(v.w * 255.f);
        int G = i >> 3, cc = i & 7;
        int w = (cc < 4) ? (8 * G + 2 * cc) : (8 * G + 2 * (cc - 4) + 1);
        qp[w] = q;
    }
#pragma unroll
    for (int o = 16; o; o >>= 1) s += __shfl_down_sync(0xffffffffu, s, o);
    __shared__ float ws[8];
    int lane = threadIdx.x & 31, w = threadIdx.x >> 5;
    if (lane == 0) ws[w] = s;
    __syncthreads();
    if (threadIdx.x == 0) {
        float d = 1.0f;  // self loop
#pragma unroll
        for (int i = 0; i < 8; i++) d += ws[i];
        d = fmaxf(d, 1.0f);
        g_dinv[row] = rsqrtf(d);
    }
}

// ---------------------------------------------------------------------------
// 2) zs = dinv ⊙ (x @ W1 + b1)   ; fp32 g_zs + colmax[0]
// ---------------------------------------------------------------------------
__global__ __launch_bounds__(256) void z1_kernel(const float* __restrict__ x,
                                                 const float* __restrict__ W1,
                                                 const float* __restrict__ b1) {
    __shared__ float Ws[IND * HID];
    __shared__ float xs[8][IND];
    __shared__ float red[256];
    int tid = threadIdx.x;
    int row0 = blockIdx.x * 8;
    for (int i = tid; i < IND * HID; i += 256) Ws[i] = W1[i];
    for (int i = tid; i < 8 * IND; i += 256)
        xs[i >> 7][i & 127] = x[(size_t)(row0 + (i >> 7)) * IND + (i & 127)];
    __syncthreads();
    int r = tid >> 5, c = tid & 31;
    float acc = b1[c];
#pragma unroll 8
    for (int k = 0; k < IND; k++) acc += xs[r][k] * Ws[k * HID + c];
    int row = row0 + r;
    float v = g_dinv[row] * acc;
    g_zs[row * HID + c] = v;
    red[tid] = fabsf(v);
    __syncthreads();
    if (tid < 128) red[tid] = fmaxf(red[tid], red[tid + 128]);
    __syncthreads();
    if (tid < 64) red[tid] = fmaxf(red[tid], red[tid + 64]);
    __syncthreads();
    if (tid < 32) atomicMax(&g_cmbits[0][tid], __float_as_uint(fmaxf(red[tid], red[tid + 32])));
}

// ---------------------------------------------------------------------------
// Quantize+transpose: g_zqT[c][j] = round(zs[j][c] * 127/cmax_c)
//   64 rows per block, 256 threads, 128 blocks (R15 proven shape)
// ---------------------------------------------------------------------------
__global__ __launch_bounds__(256) void quantT_kernel(int layer) {
    __shared__ float tile[64][HID + 1];
    __shared__ float rcp_s[HID];
    int tid = threadIdx.x;
    int row0 = blockIdx.x * 64;
    if (tid < HID)
        rcp_s[tid] = 127.f / fmaxf(__uint_as_float(g_cmbits[layer][tid]), 1e-20f);
    for (int i = tid; i < 64 * 8; i += 256) {
        int r = i >> 3, c4 = (i & 7) << 2;
        float4 v = *reinterpret_cast<const float4*>(&g_zs[(size_t)(row0 + r) * HID + c4]);
        tile[r][c4 + 0] = v.x; tile[r][c4 + 1] = v.y;
        tile[r][c4 + 2] = v.z; tile[r][c4 + 3] = v.w;
    }
    __syncthreads();
    int col = tid >> 3, jb = (tid & 7) * 8;
    float rcp = rcp_s[col];
    signed char q[8];
#pragma unroll
    for (int j = 0; j < 8; j++)
        q[j] = (signed char)__float2int_rn(tile[jb + j][col] * rcp);
    *reinterpret_cast<int2*>(&g_zqT[(size_t)col * Nn + row0 + jb]) =
        *reinterpret_cast<int2*>(q);
}

// ---------------------------------------------------------------------------
// 3+5) adjq @ zqT^T via mma m16n8k32 u8.s8, accumulated with RED.s32 into
//      g_acc[layer]. Proven config (grid 1024, 16KB B smem, one barrier,
//      depth-1 A ping-pong, permuted LDG.64 A fragments).
// ---------------------------------------------------------------------------
__global__ void __launch_bounds__(256) spmm_mma_kernel(int layer) {
    __shared__ __align__(16) unsigned char sB[HID * KCHUNK];  // 16 KB

    const int tid  = threadIdx.x;
    const int wid  = tid >> 5;
    const int lane = tid & 31;
    const int mb   = blockIdx.x >> 4;
    const int ks   = blockIdx.x & (KSPLIT - 1);
    const int row0 = mb * BM;
    const int k0   = ks * KCHUNK;
    const uint32_t sbase = smem_u32(sB);
    const int m0 = wid * 16;

    // ---- load full B chunk: 32 rows x 32 chunks of 16B, swizzle chunk^row ----
#pragma unroll
    for (int i = 0; i < 4; i++) {
        const int idx = tid + i * 256;
        const int n = idx >> 5, ch = idx & 31;
        cp16(sbase + (uint32_t)(n * KCHUNK + ((ch ^ n) << 4)),
             g_zqT + (size_t)n * Nn + k0 + ch * 16);
    }
    asm volatile("cp.async.commit_group;" ::: "memory");

    // permuted A: (a0,a2) for group G at byte 32G + 8*(lane&3)
    const unsigned char* aP =
        g_adjq + (size_t)(row0 + m0 + (lane >> 2)) * Nn + k0 + 8 * (lane & 3);
    const int nA = ((lane >> 4) << 3) + (lane & 7);
    const int cb = (lane >> 3) & 1;

    asm volatile("cp.async.wait_group 0;" ::: "memory");
    __syncthreads();   // the ONLY barrier

    int c[4][4];
#pragma unroll
    for (int nt = 0; nt < 4; nt++)
#pragma unroll
        for (int j = 0; j < 4; j++) c[nt][j] = 0;

    uint2 A0[4], A1[4];
#define LDA(dst, T)                                                              \
    {                                                                            \
        const unsigned char* p = aP + (T) * 64;                                  \
        dst[0] = __ldg(reinterpret_cast<const uint2*>(p));                       \
        dst[1] = __ldg(reinterpret_cast<const uint2*>(p + (size_t)8 * Nn));      \
        dst[2] = __ldg(reinterpret_cast<const uint2*>(p + 32));                  \
        dst[3] = __ldg(reinterpret_cast<const uint2*>(p + 32 + (size_t)8 * Nn)); \
    }

    LDA(A0, 0)

#pragma unroll
    for (int t = 0; t < NTILE; t++) {
        uint2* Ac = (t & 1) ? A1 : A0;
        uint2* An = (t & 1) ? A0 : A1;
        if (t + 1 < NTILE) LDA(An, t + 1)

#pragma unroll
        for (int kk = 0; kk < 2; kk++) {
            const int cL = t * 4 + kk * 2 + cb;
            uint32_t b[4][2];
#pragma unroll
            for (int half = 0; half < 2; half++) {
                const int n = half * 16 + nA;
                const uint32_t addr = sbase + (uint32_t)(n * KCHUNK + ((cL ^ n) << 4));
                asm volatile(
                    "ldmatrix.sync.aligned.m8n8.x4.shared.b16 {%0,%1,%2,%3}, [%4];"
                    : "=r"(b[half * 2][0]), "=r"(b[half * 2][1]),
                      "=r"(b[half * 2 + 1][0]), "=r"(b[half * 2 + 1][1])
                    : "r"(addr));
            }
            const uint32_t a0 = Ac[2 * kk].x, a1 = Ac[2 * kk + 1].x;
            const uint32_t a2 = Ac[2 * kk].y, a3 = Ac[2 * kk + 1].y;
#pragma unroll
            for (int nt = 0; nt < 4; nt++) {
                asm volatile(
                    "mma.sync.aligned.m16n8k32.row.col.s32.u8.s8.s32 "
                    "{%0,%1,%2,%3}, {%4,%5,%6,%7}, {%8,%9}, {%0,%1,%2,%3};"
                    : "+r"(c[nt][0]), "+r"(c[nt][1]), "+r"(c[nt][2]), "+r"(c[nt][3])
                    : "r"(a0), "r"(a1), "r"(a2), "r"(a3),
                      "r"(b[nt][0]), "r"(b[nt][1]));
            }
        }
    }
#undef LDA

    // accumulate s32 results (m16n8 C lane layout) via RED.s32 — exact & assoc.
    int* pp = g_acc[layer];
    const int g  = lane >> 2;
    const int tg = lane & 3;
    const int rbase = row0 + m0;
#pragma unroll
    for (int nt = 0; nt < 4; nt++) {
        const int col = nt * 8 + tg * 2;
        atomicAdd(&pp[(size_t)(rbase + g) * HID + col],     c[nt][0]);
        atomicAdd(&pp[(size_t)(rbase + g) * HID + col + 1], c[nt][1]);
        atomicAdd(&pp[(size_t)(rbase + g + 8) * HID + col],     c[nt][2]);
        atomicAdd(&pp[(size_t)(rbase + g + 8) * HID + col + 1], c[nt][3]);
    }
}

// ---------------------------------------------------------------------------
// Fused: h = relu(dinv⊙(dequant(acc0)+zs));  zs' = dinv⊙(h@W2+b2); colmax[1]
//        16 rows per block, 128 threads, grid 512.
// ---------------------------------------------------------------------------
__global__ __launch_bounds__(128) void epi1_z2_kernel(const float* __restrict__ W2,
                                                      const float* __restrict__ b2) {
    __shared__ float hs[16][HID + 1];
    __shared__ float W2s[HID * HID];
    __shared__ unsigned cm[HID];
    int tid = threadIdx.x;
    int r = tid >> 3;             // 0..15
    int c0 = (tid & 7) << 2;
    int row = blockIdx.x * 16 + r;
    int idx4 = (row * HID + c0) >> 2;

    for (int i = tid; i < HID * HID; i += 128) W2s[i] = W2[i];
    if (tid < HID) cm[tid] = 0u;

    int4 S = reinterpret_cast<const int4*>(g_acc[0])[idx4];
    float4 zs = reinterpret_cast<const float4*>(g_zs)[idx4];
    float di = g_dinv[row];
    const float inv = 1.0f / 32385.0f;  // 1/(127*255)
    float f0 = __uint_as_float(g_cmbits[0][c0 + 0]) * inv;
    float f1 = __uint_as_float(g_cmbits[0][c0 + 1]) * inv;
    float f2 = __uint_as_float(g_cmbits[0][c0 + 2]) * inv;
    float f3 = __uint_as_float(g_cmbits[0][c0 + 3]) * inv;
    hs[r][c0 + 0] = fmaxf(di * (S.x * f0 + zs.x), 0.f);
    hs[r][c0 + 1] = fmaxf(di * (S.y * f1 + zs.y), 0.f);
    hs[r][c0 + 2] = fmaxf(di * (S.z * f2 + zs.z), 0.f);
    hs[r][c0 + 3] = fmaxf(di * (S.w * f3 + zs.w), 0.f);
    __syncthreads();

    float acc[4] = { b2[c0], b2[c0 + 1], b2[c0 + 2], b2[c0 + 3] };
#pragma unroll
    for (int k = 0; k < HID; k++) {
        float hv = hs[r][k];
        acc[0] += hv * W2s[k * HID + c0 + 0];
        acc[1] += hv * W2s[k * HID + c0 + 1];
        acc[2] += hv * W2s[k * HID + c0 + 2];
        acc[3] += hv * W2s[k * HID + c0 + 3];
    }
    float4 o;
    o.x = di * acc[0]; o.y = di * acc[1]; o.z = di * acc[2]; o.w = di * acc[3];
    reinterpret_cast<float4*>(g_zs)[idx4] = o;
    atomicMax(&cm[c0 + 0], __float_as_uint(fabsf(o.x)));
    atomicMax(&cm[c0 + 1], __float_as_uint(fabsf(o.y)));
    atomicMax(&cm[c0 + 2], __float_as_uint(fabsf(o.z)));
    atomicMax(&cm[c0 + 3], __float_as_uint(fabsf(o.w)));
    __syncthreads();
    if (tid < HID) atomicMax(&g_cmbits[1][tid], cm[tid]);
}

// ---------------------------------------------------------------------------
// Epilogue L2 + final: logits = relu(dinv⊙(dequant(acc1)+zs)) @ W3 + b3
// ---------------------------------------------------------------------------
__global__ __launch_bounds__(128) void epilogue_final_kernel(const float* __restrict__ W3,
                                                             const float* __restrict__ b3,
                                                             float* __restrict__ out) {
    int tid = threadIdx.x;
    int idx4 = blockIdx.x * 128 + tid;
    int row = idx4 >> 3;
    int c0 = (idx4 & 7) << 2;
    int4 S = reinterpret_cast<const int4*>(g_acc[1])[idx4];
    float4 zs = reinterpret_cast<const float4*>(g_zs)[idx4];
    float di = g_dinv[row];
    const float inv = 1.0f / 32385.0f;
    float f0 = __uint_as_float(g_cmbits[1][c0 + 0]) * inv;
    float f1 = __uint_as_float(g_cmbits[1][c0 + 1]) * inv;
    float f2 = __uint_as_float(g_cmbits[1][c0 + 2]) * inv;
    float f3 = __uint_as_float(g_cmbits[1][c0 + 3]) * inv;
    float h0 = fmaxf(di * (S.x * f0 + zs.x), 0.f);
    float h1 = fmaxf(di * (S.y * f1 + zs.y), 0.f);
    float h2 = fmaxf(di * (S.z * f2 + zs.z), 0.f);
    float h3 = fmaxf(di * (S.w * f3 + zs.w), 0.f);
    float v = h0 * W3[c0] + h1 * W3[c0 + 1] + h2 * W3[c0 + 2] + h3 * W3[c0 + 3];
#pragma unroll
    for (int o = 4; o; o >>= 1) v += __shfl_xor_sync(0xffffffffu, v, o);
    if ((tid & 7) == 0) out[row] = v + b3[0];
}

// ---------------------------------------------------------------------------
extern "C" void kernel_launch(void* const* d_in, const int* in_sizes, int n_in,
                              void* d_out, int out_size) {
    const float* x   = (const float*)d_in[0];
    const float* adj = (const float*)d_in[1];
    const float* W1  = (const float*)d_in[2];
    const float* b1  = (const float*)d_in[3];
    const float* W2  = (const float*)d_in[4];
    const float* b2  = (const float*)d_in[5];
    const float* W3  = (const float*)d_in[6];
    const float* b3  = (const float*)d_in[7];
    float* out = (float*)d_out;

    degree_convert_kernel<<<Nn, 256>>>(adj);          // also zeroes g_acc
    z1_kernel<<<Nn / 8, 256>>>(x, W1, b1);
    quantT_kernel<<<Nn / 64, 256>>>(0);
    spmm_mma_kernel<<<64 * KSPLIT, 256>>>(0);         // layer 1 -> g_acc[0]
    epi1_z2_kernel<<<Nn / 16, 128>>>(W2, b2);         // h + z2 fused -> g_zs
    quantT_kernel<<<Nn / 64, 256>>>(1);
    spmm_mma_kernel<<<64 * KSPLIT, 256>>>(1);         // layer 2 -> g_acc[1]
    epilogue_final_kernel<<<Nn * HID / 4 / 128, 128>>>(W3, b3, out);
}